// round 1
// baseline (speedup 1.0000x reference)
#include <cuda_runtime.h>
#include <math.h>

// Problem constants
#define T_LEN   512
#define B_SZ    128
#define H_SZ    1024
#define NIN     128
#define NOUT    128
#define ALPHA_F 0.25f
#define LEAK_F  0.75f           // 1 - alpha
#define NSCALE  0.025f          // SIGMA_NEU * sqrt(alpha) = 0.05 * 0.5
#define GRID_RNN 128

// ---------------- scratch (device globals: no allocation allowed) ----------
__device__ float g_c[(size_t)T_LEN * B_SZ * H_SZ];   // alpha*(xW_in+b_in+b_hh)+noise, [T,B,H]
__device__ float g_h[B_SZ * H_SZ];                   // current hidden
__device__ float g_a[B_SZ * H_SZ];                   // tanh(current hidden)
__device__ float g_p[4 * B_SZ * H_SZ];               // split-K partials
__device__ unsigned g_bar_count;
__device__ unsigned g_bar_release;

// ---------------- init: h, tanh(h), barrier state ---------------------------
__global__ void init_kernel(const float* __restrict__ hidden) {
    int i = blockIdx.x * blockDim.x + threadIdx.x;
    if (i == 0) { g_bar_count = 0u; g_bar_release = 0u; }
    if (i < B_SZ * H_SZ) {
        float h = hidden[i];
        g_h[i] = h;
        g_a[i] = tanhf(h);
    }
}

// ---------------- pre: c[t,b,h] = a*(x@Win^T + b_in + b_hh) + 0.025*noise ---
// GEMM [65536 x 128] @ [128 x 1024], rows r = t*128 + b (matches noise layout)
__global__ void __launch_bounds__(256) pre_kernel(
    const float* __restrict__ x,        // [B,T,NIN]
    const float* __restrict__ noise,    // [T,B,H]
    const float* __restrict__ w_in,     // [H,NIN]
    const float* __restrict__ b_in,     // [H]
    const float* __restrict__ b_hh)     // [H]
{
    __shared__ float As[16][68];
    __shared__ float Bs[16][68];
    int tid = threadIdx.x;
    int tr = tid >> 4, tc = tid & 15;
    int lr = tid >> 2, lk = (tid & 3) * 4;
    int r0 = blockIdx.x * 64;
    int c0 = blockIdx.y * 64;
    float acc[4][4] = {};

    int rA = r0 + lr;
    int tt = rA >> 7;          // r / 128
    int bb = rA & 127;         // r % 128
    const float* arow = x + ((size_t)bb * T_LEN + tt) * NIN;
    const float* brow = w_in + (size_t)(c0 + lr) * NIN;

    for (int ko = 0; ko < NIN; ko += 16) {
        float4 av = *(const float4*)(arow + ko + lk);
        float4 bv = *(const float4*)(brow + ko + lk);
        __syncthreads();
        As[lk + 0][lr] = av.x; As[lk + 1][lr] = av.y;
        As[lk + 2][lr] = av.z; As[lk + 3][lr] = av.w;
        Bs[lk + 0][lr] = bv.x; Bs[lk + 1][lr] = bv.y;
        Bs[lk + 2][lr] = bv.z; Bs[lk + 3][lr] = bv.w;
        __syncthreads();
        #pragma unroll
        for (int kk = 0; kk < 16; kk++) {
            float a[4], b[4];
            *(float4*)a = *(float4*)&As[kk][tr * 4];
            *(float4*)b = *(float4*)&Bs[kk][tc * 4];
            #pragma unroll
            for (int i = 0; i < 4; i++)
                #pragma unroll
                for (int j = 0; j < 4; j++)
                    acc[i][j] = fmaf(a[i], b[j], acc[i][j]);
        }
    }

    int c = c0 + tc * 4;
    float bi0 = b_in[c + 0] + b_hh[c + 0];
    float bi1 = b_in[c + 1] + b_hh[c + 1];
    float bi2 = b_in[c + 2] + b_hh[c + 2];
    float bi3 = b_in[c + 3] + b_hh[c + 3];
    #pragma unroll
    for (int i = 0; i < 4; i++) {
        int r = r0 + tr * 4 + i;
        size_t off = (size_t)r * H_SZ + c;
        float4 nv = *(const float4*)(noise + off);
        float4 v;
        v.x = ALPHA_F * (acc[i][0] + bi0) + NSCALE * nv.x;
        v.y = ALPHA_F * (acc[i][1] + bi1) + NSCALE * nv.y;
        v.z = ALPHA_F * (acc[i][2] + bi2) + NSCALE * nv.z;
        v.w = ALPHA_F * (acc[i][3] + bi3) + NSCALE * nv.w;
        *(float4*)(g_c + off) = v;
    }
}

// ---------------- grid barrier (cumulative-count, sense-free) ---------------
__device__ __forceinline__ void grid_bar(unsigned target) {
    __syncthreads();
    if (threadIdx.x == 0) {
        __threadfence();
        unsigned arrived = atomicAdd(&g_bar_count, 1u) + 1u;
        if (arrived == target * (unsigned)GRID_RNN) {
            __threadfence();
            atomicExch(&g_bar_release, target);
        } else {
            while (*(volatile unsigned*)&g_bar_release < target) {
                __nanosleep(64);
            }
        }
        __threadfence();
    }
    __syncthreads();
}

// ---------------- recurrent persistent kernel --------------------------------
// 128 CTAs = 2 b-tiles x 16 h-tiles x 4 k-splits. Per step:
//   phase G: partial tile (64x64 over K=256) of tanh(h) @ Whh^T -> g_p
//   barrier
//   phase U: each CTA owns 1024 elements: h' = 0.75h + 0.25*sum(partials) + c[t]
//            write g_h, g_a=tanh(h'), hidden_list[b,t,:], (h_final at t=511)
//   barrier
__global__ void __launch_bounds__(256) rnn_kernel(
    float* __restrict__ hid_list,       // [B,T,H] section of d_out
    float* __restrict__ h_final,        // [B,H]   section of d_out
    const float* __restrict__ w_hh)     // [H,H]
{
    __shared__ float As[16][68];
    __shared__ float Bs[16][68];
    int cta = blockIdx.x;
    int ks = cta & 3;
    int bt = (cta >> 2) & 1;
    int ht = cta >> 3;
    int tid = threadIdx.x;
    int tr = tid >> 4, tc = tid & 15;
    int lr = tid >> 2, lk = (tid & 3) * 4;
    int r0 = bt * 64, c0 = ht * 64, k0 = ks * 256;

    const float* arow = g_a + (size_t)(r0 + lr) * H_SZ;
    const float* brow = w_hh + (size_t)(c0 + lr) * H_SZ;
    float* pout = g_p + (size_t)ks * (B_SZ * H_SZ);

    int e  = cta * 1024 + tid * 4;      // update-phase element base
    int eb = e >> 10;                   // batch index
    int eh = e & 1023;                  // hidden index
    unsigned epoch = 0;

    for (int t = 0; t < T_LEN; t++) {
        // ---- phase G: split-K GEMM partial ----
        float acc[4][4] = {};
        for (int ko = k0; ko < k0 + 256; ko += 16) {
            float4 av = *(const float4*)(arow + ko + lk);
            float4 bv = *(const float4*)(brow + ko + lk);
            __syncthreads();
            As[lk + 0][lr] = av.x; As[lk + 1][lr] = av.y;
            As[lk + 2][lr] = av.z; As[lk + 3][lr] = av.w;
            Bs[lk + 0][lr] = bv.x; Bs[lk + 1][lr] = bv.y;
            Bs[lk + 2][lr] = bv.z; Bs[lk + 3][lr] = bv.w;
            __syncthreads();
            #pragma unroll
            for (int kk = 0; kk < 16; kk++) {
                float a[4], b[4];
                *(float4*)a = *(float4*)&As[kk][tr * 4];
                *(float4*)b = *(float4*)&Bs[kk][tc * 4];
                #pragma unroll
                for (int i = 0; i < 4; i++)
                    #pragma unroll
                    for (int j = 0; j < 4; j++)
                        acc[i][j] = fmaf(a[i], b[j], acc[i][j]);
            }
        }
        #pragma unroll
        for (int i = 0; i < 4; i++) {
            float4 v = make_float4(acc[i][0], acc[i][1], acc[i][2], acc[i][3]);
            *(float4*)(pout + (size_t)(r0 + tr * 4 + i) * H_SZ + c0 + tc * 4) = v;
        }

        grid_bar(++epoch);

        // ---- phase U: element-owner update ----
        {
            float4 p0 = *(const float4*)(g_p + e);
            float4 p1 = *(const float4*)(g_p + 1 * B_SZ * H_SZ + e);
            float4 p2 = *(const float4*)(g_p + 2 * B_SZ * H_SZ + e);
            float4 p3 = *(const float4*)(g_p + 3 * B_SZ * H_SZ + e);
            float4 hc = *(const float4*)(g_h + e);
            float4 cv = *(const float4*)(g_c + (size_t)t * (B_SZ * H_SZ) + e);
            float4 hn;
            hn.x = LEAK_F * hc.x + ALPHA_F * (p0.x + p1.x + p2.x + p3.x) + cv.x;
            hn.y = LEAK_F * hc.y + ALPHA_F * (p0.y + p1.y + p2.y + p3.y) + cv.y;
            hn.z = LEAK_F * hc.z + ALPHA_F * (p0.z + p1.z + p2.z + p3.z) + cv.z;
            hn.w = LEAK_F * hc.w + ALPHA_F * (p0.w + p1.w + p2.w + p3.w) + cv.w;
            *(float4*)(g_h + e) = hn;
            float4 an = make_float4(tanhf(hn.x), tanhf(hn.y), tanhf(hn.z), tanhf(hn.w));
            *(float4*)(g_a + e) = an;
            *(float4*)(hid_list + ((size_t)eb * T_LEN + t) * H_SZ + eh) = hn;
            if (t == T_LEN - 1) {
                *(float4*)(h_final + e) = hn;
            }
        }

        grid_bar(++epoch);
    }
}

// ---------------- post: out[b,t,o] = clip(hid @ Wout^T + b_out) -------------
// GEMM [65536 x 1024] @ [1024 x 128]
__global__ void __launch_bounds__(256) post_kernel(
    const float* __restrict__ hid_list, // [B,T,H]  (rows q = b*T+t)
    const float* __restrict__ w_out,    // [NOUT,H]
    const float* __restrict__ b_out,    // [NOUT]
    float* __restrict__ out_list)       // [B,T,NOUT]
{
    __shared__ float As[16][68];
    __shared__ float Bs[16][68];
    int tid = threadIdx.x;
    int tr = tid >> 4, tc = tid & 15;
    int lr = tid >> 2, lk = (tid & 3) * 4;
    int r0 = blockIdx.x * 64;
    int c0 = blockIdx.y * 64;
    float acc[4][4] = {};

    const float* arow = hid_list + (size_t)(r0 + lr) * H_SZ;
    const float* brow = w_out + (size_t)(c0 + lr) * H_SZ;

    for (int ko = 0; ko < H_SZ; ko += 16) {
        float4 av = *(const float4*)(arow + ko + lk);
        float4 bv = *(const float4*)(brow + ko + lk);
        __syncthreads();
        As[lk + 0][lr] = av.x; As[lk + 1][lr] = av.y;
        As[lk + 2][lr] = av.z; As[lk + 3][lr] = av.w;
        Bs[lk + 0][lr] = bv.x; Bs[lk + 1][lr] = bv.y;
        Bs[lk + 2][lr] = bv.z; Bs[lk + 3][lr] = bv.w;
        __syncthreads();
        #pragma unroll
        for (int kk = 0; kk < 16; kk++) {
            float a[4], b[4];
            *(float4*)a = *(float4*)&As[kk][tr * 4];
            *(float4*)b = *(float4*)&Bs[kk][tc * 4];
            #pragma unroll
            for (int i = 0; i < 4; i++)
                #pragma unroll
                for (int j = 0; j < 4; j++)
                    acc[i][j] = fmaf(a[i], b[j], acc[i][j]);
        }
    }

    int c = c0 + tc * 4;
    float bo0 = b_out[c + 0], bo1 = b_out[c + 1];
    float bo2 = b_out[c + 2], bo3 = b_out[c + 3];
    #pragma unroll
    for (int i = 0; i < 4; i++) {
        int r = r0 + tr * 4 + i;
        float4 v;
        v.x = fminf(fmaxf(acc[i][0] + bo0, -20.0f), 20.0f);
        v.y = fminf(fmaxf(acc[i][1] + bo1, -20.0f), 20.0f);
        v.z = fminf(fmaxf(acc[i][2] + bo2, -20.0f), 20.0f);
        v.w = fminf(fmaxf(acc[i][3] + bo3, -20.0f), 20.0f);
        *(float4*)(out_list + (size_t)r * NOUT + c) = v;
    }
}

// ---------------- launch ------------------------------------------------------
extern "C" void kernel_launch(void* const* d_in, const int* in_sizes, int n_in,
                              void* d_out, int out_size) {
    const float* x        = (const float*)d_in[0]; // [B,T,NIN]
    const float* hidden0  = (const float*)d_in[1]; // [B,H]
    const float* noise    = (const float*)d_in[2]; // [T,B,H]
    const float* w_in_w   = (const float*)d_in[3]; // [H,NIN]
    const float* w_in_b   = (const float*)d_in[4]; // [H]
    const float* w_hh_w   = (const float*)d_in[5]; // [H,H]
    const float* w_hh_b   = (const float*)d_in[6]; // [H]
    const float* w_out_w  = (const float*)d_in[7]; // [NOUT,H]
    const float* w_out_b  = (const float*)d_in[8]; // [NOUT]

    float* out      = (float*)d_out;
    float* hid_list = out;                                        // [B,T,H]
    float* out_list = out + (size_t)B_SZ * T_LEN * H_SZ;          // [B,T,NOUT]
    float* h_final  = out_list + (size_t)B_SZ * T_LEN * NOUT;     // [B,H]

    init_kernel<<<(B_SZ * H_SZ + 255) / 256, 256>>>(hidden0);
    pre_kernel<<<dim3((T_LEN * B_SZ) / 64, H_SZ / 64), 256>>>(
        x, noise, w_in_w, w_in_b, w_hh_b);
    rnn_kernel<<<GRID_RNN, 256>>>(hid_list, h_final, w_hh_w);
    post_kernel<<<dim3((B_SZ * T_LEN) / 64, NOUT / 64), 256>>>(
        hid_list, w_out_w, w_out_b, out_list);
}